// round 13
// baseline (speedup 1.0000x reference)
#include <cuda_runtime.h>
#include <cuda_fp16.h>

#define NN 100000
#define NE 1000000

// Scratch.
// P1h row (128B) parity-split: half p (byte offset 64p) = 32 halfs:
//   [0..19]  P[5p+oo][k] (oo<5,k<4)   [20..24] Q[5p+oo]
//   [25..29] root1[5p+oo] (fp16)      [30..31] pad
// g_S row: attr-sum[0..3], deg at [4] (8-float rows, zeroed by memset node)
// g_red[0..59]: v[i]=g_red[i]; T[i][k]=g_red[10+i*5+k]. g_red[64]: block counter.
__device__ float4 g_P1h[(size_t)NN * 8];
__device__ float4 g_S  [(size_t)NN * 2];
__device__ float  g_red[68];

// ---------------------------------------------------------------------------
// Per-warp dtype sniff: int64 iff the first 32 int64-interpreted entries are
// all in [0, n). (int32 data viewed as int64 fuses two random indices ->
// ~2^48 magnitude -> fails with overwhelming probability.)
// ---------------------------------------------------------------------------
__device__ __forceinline__ int sniff_is64(const void* ei, int ec, int n)
{
    const long long* p = (const long long*)ei;
    int lane = threadIdx.x & 31;
    int m = ec < 32 ? ec : 32;
    long long v = __ldg(&p[lane < m ? lane : 0]);
    unsigned bad = __ballot_sync(0xffffffffu, v < 0 || v >= n);
    return bad == 0u;
}

// ---------------------------------------------------------------------------
// k_mid: block-role split.
//  node role (blocks < nodeBlocks): 128 nodes/block, 2 thr/node (parity):
//    writes parity-split P/Q/root1 (fp16) rows; block-reduces v_root -> g_red.
//  edge role: S[src] += (attr, 1) via vectorized REDs (self-sniffed dtype).
// ---------------------------------------------------------------------------
__global__ void k_mid(const float* __restrict__ x,
                      const float* __restrict__ W1e, const float* __restrict__ b1e,
                      const float* __restrict__ Wr1, const float* __restrict__ bb1,
                      const void* __restrict__ ei, const float4* __restrict__ attr,
                      int n, int ec, int nodeBlocks)
{
    if (blockIdx.x >= nodeBlocks) {
        int is64 = sniff_is64(ei, ec, n);
        int e = (blockIdx.x - nodeBlocks) * blockDim.x + threadIdx.x;
        if (e >= ec) return;
        int src;
        if (is64) src = (int)__ldg(&((const long long*)ei)[e]);
        else      src = __ldg(&((const int*)ei)[e]);
        float4 a = __ldg(&attr[e]);
        float* s = (float*)(g_S + (size_t)src * 2);
        asm volatile("red.global.add.v4.f32 [%0], {%1,%2,%3,%4};"
                     :: "l"(s), "f"(a.x), "f"(a.y), "f"(a.z), "f"(a.w) : "memory");
        asm volatile("red.global.add.f32 [%0], %1;"
                     :: "l"(s + 4), "f"(1.0f) : "memory");
        return;
    }

    __shared__ float sW[720], sB[180], sWr[180], sBB[16];
    __shared__ float sx[128 * 18];
    __shared__ float s_v[10];
    for (int i = threadIdx.x; i < 720; i += blockDim.x) sW[i] = W1e[i];
    for (int i = threadIdx.x; i < 180; i += blockDim.x) { sB[i] = b1e[i]; sWr[i] = Wr1[i]; }
    if (threadIdx.x < 10) { sBB[threadIdx.x] = bb1[threadIdx.x]; s_v[threadIdx.x] = 0.f; }

    int nd0 = blockIdx.x * 128;
    int cnt = n - nd0; if (cnt > 128) cnt = 128;
    for (int i = threadIdx.x; i < cnt * 18; i += blockDim.x)
        sx[i] = __ldg(&x[(size_t)nd0 * 18 + i]);
    __syncthreads();

    int ndl  = threadIdx.x >> 1;
    int half = threadIdx.x & 1;
    if (ndl < cnt) {
        int nd = nd0 + ndl;
        float xv[18];
        #pragma unroll
        for (int i = 0; i < 18; i++) xv[i] = sx[ndl * 18 + i];

        __half*  ph  = (__half*)(g_P1h + (size_t)nd * 8) + 32 * half;
        __half2* ph2 = (__half2*)ph;

        int o0 = half * 5;
        #pragma unroll
        for (int oo = 0; oo < 5; oo++) {
            int o = o0 + oo;
            float p0 = 0.f, p1 = 0.f, p2 = 0.f, p3 = 0.f, q = 0.f, h = 0.f;
            #pragma unroll
            for (int i = 0; i < 18; i++) {
                int r = i * 10 + o;
                float xi = xv[i];
                p0 += xi * sW[r * 4 + 0];
                p1 += xi * sW[r * 4 + 1];
                p2 += xi * sW[r * 4 + 2];
                p3 += xi * sW[r * 4 + 3];
                q  += xi * sB[r];
                h  += xi * sWr[r];
            }
            float hval = h + sBB[o];
            ph2[oo * 2 + 0] = __floats2half2_rn(p0, p1);
            ph2[oo * 2 + 1] = __floats2half2_rn(p2, p3);
            ph[20 + oo]     = __float2half_rn(q);
            ph[25 + oo]     = __float2half_rn(hval);
            atomicAdd(&s_v[o], hval);          // v_root block partial
        }
    }
    __syncthreads();
    if (threadIdx.x < 10) atomicAdd(&g_red[threadIdx.x], s_v[threadIdx.x]);
}

// ---------------------------------------------------------------------------
// k_tail: pure edge phase, 2 lanes per edge (parity p owns channels 5p..5p+4).
//   m[oo]  = Q + sum_k attr[k]*P[oo][k]          (message)
//   v[oo] += m;  T[oo][k] += m*S[tgt][k] + root1_src[oo]*attr[k]  (k<4)
//   T[oo][4] += m*deg[tgt] + root1_src[oo]
// One reduction tail; last block runs the MLP.
// ---------------------------------------------------------------------------
__global__ __launch_bounds__(256, 3)
void k_tail(const void* __restrict__ ei, const float4* __restrict__ attr,
            const float* __restrict__ Wr2, const float* __restrict__ bb2,
            const float* __restrict__ W2e, const float* __restrict__ b2e,
            const float* __restrict__ w1, const float* __restrict__ bw1,
            const float* __restrict__ w2, const float* __restrict__ bw2,
            const float* __restrict__ w3, const float* __restrict__ bw3,
            float* __restrict__ out, int n, int ec, int out_size)
{
    __shared__ float s_acc[64];
    if (threadIdx.x < 64) s_acc[threadIdx.x] = 0.f;
    __syncthreads();

    const int is64 = sniff_is64(ei, ec, n);
    const int p = threadIdx.x & 1;
    const int pairId = (blockIdx.x * blockDim.x + threadIdx.x) >> 1;
    const int pairStride = (gridDim.x * blockDim.x) >> 1;

    float v[5];
    float T[25];
    #pragma unroll
    for (int i = 0; i < 5; i++) v[i] = 0.f;
    #pragma unroll
    for (int i = 0; i < 25; i++) T[i] = 0.f;

    for (int e = pairId; e < ec; e += pairStride) {
        int src, tgt;
        if (is64) {
            src = (int)__ldg(&((const long long*)ei)[e]);
            tgt = (int)__ldg(&((const long long*)ei)[(size_t)ec + e]);
        } else {
            src = __ldg(&((const int*)ei)[e]);
            tgt = __ldg(&((const int*)ei)[(size_t)ec + e]);
        }
        float4 a = __ldg(&attr[e]);

        const char* base = (const char*)(g_P1h + (size_t)src * 8) + 64 * p;
        float4 A = __ldg((const float4*)base);
        float4 B = __ldg((const float4*)(base + 16));
        float4 C = __ldg((const float4*)(base + 32));
        float4 D = __ldg((const float4*)(base + 48));

        const __half2* hA = (const __half2*)&A;
        const __half2* hB = (const __half2*)&B;
        const __half2* hC = (const __half2*)&C;
        const __half2* hD = (const __half2*)&D;

        float2 a0 = __half22float2(hA[0]), a1 = __half22float2(hA[1]);
        float2 a2 = __half22float2(hA[2]), a3 = __half22float2(hA[3]);
        float2 b0 = __half22float2(hB[0]), b1 = __half22float2(hB[1]);
        float2 b2 = __half22float2(hB[2]), b3 = __half22float2(hB[3]);
        float2 c0 = __half22float2(hC[0]), c1 = __half22float2(hC[1]);
        float2 q01 = __half22float2(hC[2]);   // Q0,Q1
        float2 q23 = __half22float2(hC[3]);   // Q2,Q3
        float2 d0 = __half22float2(hD[0]);    // Q4, r0
        float2 d1 = __half22float2(hD[1]);    // r1, r2
        float2 d2 = __half22float2(hD[2]);    // r3, r4

        float m[5], r[5];
        m[0] = a.x * a0.x + a.y * a0.y + a.z * a1.x + a.w * a1.y + q01.x;
        m[1] = a.x * a2.x + a.y * a2.y + a.z * a3.x + a.w * a3.y + q01.y;
        m[2] = a.x * b0.x + a.y * b0.y + a.z * b1.x + a.w * b1.y + q23.x;
        m[3] = a.x * b2.x + a.y * b2.y + a.z * b3.x + a.w * b3.y + q23.y;
        m[4] = a.x * c0.x + a.y * c0.y + a.z * c1.x + a.w * c1.y + d0.x;
        r[0] = d0.y; r[1] = d1.x; r[2] = d1.y; r[3] = d2.x; r[4] = d2.y;

        const float* sr = (const float*)(g_S + (size_t)tgt * 2);
        float4 s4 = __ldg((const float4*)sr);
        float  sd = __ldg(sr + 4);

        #pragma unroll
        for (int oo = 0; oo < 5; oo++) {
            float mi = m[oo], ri = r[oo];
            v[oo] += mi;
            T[oo * 5 + 0] += mi * s4.x + ri * a.x;
            T[oo * 5 + 1] += mi * s4.y + ri * a.y;
            T[oo * 5 + 2] += mi * s4.z + ri * a.z;
            T[oo * 5 + 3] += mi * s4.w + ri * a.w;
            T[oo * 5 + 4] += mi * sd   + ri;
        }
    }

    // ---- reduce: fold lanes of equal parity; lanes 0,1 hold warp totals ----
    #pragma unroll
    for (int off = 2; off <= 16; off <<= 1) {
        #pragma unroll
        for (int i = 0; i < 5; i++)  v[i] += __shfl_xor_sync(0xffffffffu, v[i], off);
        #pragma unroll
        for (int i = 0; i < 25; i++) T[i] += __shfl_xor_sync(0xffffffffu, T[i], off);
    }
    int lane = threadIdx.x & 31;
    if (lane < 2) {
        #pragma unroll
        for (int oo = 0; oo < 5; oo++) {
            int i = 5 * lane + oo;
            atomicAdd(&s_acc[i], v[oo]);
            #pragma unroll
            for (int k = 0; k < 5; k++)
                atomicAdd(&s_acc[10 + i * 5 + k], T[oo * 5 + k]);
        }
    }
    __syncthreads();
    if (threadIdx.x < 60) atomicAdd(&g_red[threadIdx.x], s_acc[threadIdx.x]);
    __threadfence();
    __syncthreads();

    // ---- last block: MLP ----
    __shared__ int isLast;
    if (threadIdx.x == 0) {
        unsigned int prev = atomicAdd((unsigned int*)&g_red[64], 1u);
        isLast = (prev == gridDim.x - 1) ? 1 : 0;
    }
    __syncthreads();
    if (!isLast) return;

    volatile float* gr = g_red;
    __shared__ float g[8];
    float invn = 1.0f / (float)n;
    if (threadIdx.x < 7) {
        int o = threadIdx.x;
        float s = (float)n * bb2[o];
        #pragma unroll
        for (int i = 0; i < 10; i++) {
            float vi = gr[i];
            s += vi * Wr2[i * 7 + o];
            int rr = i * 7 + o;
            #pragma unroll
            for (int k = 0; k < 4; k++) s += gr[10 + i * 5 + k] * W2e[rr * 4 + k];
            s += gr[10 + i * 5 + 4] * b2e[rr];
        }
        g[o] = s * invn;
    }
    __syncthreads();
    if (threadIdx.x == 0) {
        float gg[7];
        #pragma unroll
        for (int k = 0; k < 7; k++) gg[k] = g[k];
        float g1[20];
        for (int j = 0; j < 20; j++) {
            float val = bw1[j];
            #pragma unroll
            for (int k = 0; k < 7; k++) val += gg[k] * w1[j * 7 + k];
            g1[j] = val > 0.f ? val : 0.f;
        }
        float g2[10];
        for (int j = 0; j < 10; j++) {
            float val = bw2[j];
            #pragma unroll
            for (int k = 0; k < 20; k++) val += g1[k] * w2[j * 20 + k];
            g2[j] = val > 0.f ? val : 0.f;
        }
        float z = bw3[0];
        #pragma unroll
        for (int k = 0; k < 10; k++) z += g2[k] * w3[k];
        float rr = 1.0f / (1.0f + expf(-z));
        for (int i = 0; i < out_size; i++) out[i] = rr;
    }
}

// ---------------------------------------------------------------------------
extern "C" void kernel_launch(void* const* d_in, const int* in_sizes, int n_in,
                              void* d_out, int out_size)
{
    const float*  x    = (const float*)d_in[0];
    const void*   ei   = d_in[1];
    const float4* attr = (const float4*)d_in[2];
    const float* W1e = (const float*)d_in[3];
    const float* b1e = (const float*)d_in[4];
    const float* Wr1 = (const float*)d_in[5];
    const float* bb1 = (const float*)d_in[6];
    const float* W2e = (const float*)d_in[7];
    const float* b2e = (const float*)d_in[8];
    const float* Wr2 = (const float*)d_in[9];
    const float* bb2 = (const float*)d_in[10];
    const float* w1  = (const float*)d_in[11];
    const float* bw1 = (const float*)d_in[12];
    const float* w2  = (const float*)d_in[13];
    const float* bw2 = (const float*)d_in[14];
    const float* w3  = (const float*)d_in[15];
    const float* bw3 = (const float*)d_in[16];

    int n = in_sizes[0] / 18;
    int e = in_sizes[2] / 4;
    if (n > NN) n = NN;
    if (e > NE) e = NE;

    // Graph-capturable memset nodes replace the zero kernel.
    void* sPtr = nullptr;
    void* rPtr = nullptr;
    cudaGetSymbolAddress(&sPtr, g_S);
    cudaGetSymbolAddress(&rPtr, g_red);
    cudaMemsetAsync(sPtr, 0, (size_t)n * 2 * sizeof(float4), 0);
    cudaMemsetAsync(rPtr, 0, 68 * sizeof(float), 0);

    const int T = 256;
    int nodeBlocks = (n + 127) / 128;
    int edgeBlocks = (e + T - 1) / T;

    k_mid<<<nodeBlocks + edgeBlocks, T>>>(x, W1e, b1e, Wr1, bb1, ei, attr,
                                          n, e, nodeBlocks);
    k_tail<<<444, T>>>(ei, attr, Wr2, bb2, W2e, b2e, w1, bw1, w2, bw2, w3, bw3,
                       (float*)d_out, n, e, out_size);
}

// round 14
// speedup vs baseline: 1.3665x; 1.3665x over previous
#include <cuda_runtime.h>
#include <cuda_fp16.h>

#define NN 100000
#define NE 1000000

// Scratch.
// P1h row (128B, 64 halfs) parity-split: half p (byte offset 64p) holds
//   halfs[0..19]  = P[5p+oo][k]  (oo<5, k<4, index oo*4+k)
//   halfs[20..24] = Q[5p+oo]
//   halfs[25..31] = pad
// g_h1 row (16 floats) parity-split: floats[8p+oo] = root1[5p+oo] (oo<5)
// g_S row: attr-sum[0..3], deg at [4] (floats 5..7 stay zero)
__device__ float4 g_P1h[(size_t)NN * 8];
__device__ float4 g_h1 [(size_t)NN * 4];
__device__ float4 g_S  [(size_t)NN * 2];
__device__ float  g_red[64];  // v[i]=g_red[i] (i<10); T[i][k]=g_red[10+i*5+k]
__device__ int    g_is64;
__device__ unsigned int g_count;

// ---------------------------------------------------------------------------
// k_zero: zero S + g_red + count; dtype sniff (block 0).
// ---------------------------------------------------------------------------
__global__ void k_zero(const void* __restrict__ ei, int ec, int n)
{
    int tid = blockIdx.x * blockDim.x + threadIdx.x;
    float4 z = make_float4(0.f, 0.f, 0.f, 0.f);
    for (int i = tid; i < 2 * n; i += gridDim.x * blockDim.x) g_S[i] = z;
    if (blockIdx.x == 0) {
        if (threadIdx.x < 64) g_red[threadIdx.x] = 0.f;
        if (threadIdx.x == 64) g_count = 0u;
        __shared__ int ok;
        if (threadIdx.x == 0) ok = 1;
        __syncthreads();
        const long long* p = (const long long*)ei;
        int m = ec < 128 ? ec : 128;
        if (threadIdx.x < m) {
            long long v = p[threadIdx.x];
            if (v < 0 || v >= n) ok = 0;
        }
        __syncthreads();
        if (threadIdx.x == 0) g_is64 = ok;
    }
}

// ---------------------------------------------------------------------------
// k_mid: block-role split.
//  node role: 128 nodes/block, 2 thr/node (thread = one parity half):
//    writes parity-split P/Q (fp16) and parity-split root1 (f32).
//  edge role: S[src] += (attr, 1) via vectorized REDs.
// ---------------------------------------------------------------------------
__global__ void k_mid(const float* __restrict__ x,
                      const float* __restrict__ W1e, const float* __restrict__ b1e,
                      const float* __restrict__ Wr1, const float* __restrict__ bb1,
                      const void* __restrict__ ei, const float4* __restrict__ attr,
                      int n, int ec, int nodeBlocks)
{
    if (blockIdx.x >= nodeBlocks) {
        int e = (blockIdx.x - nodeBlocks) * blockDim.x + threadIdx.x;
        if (e >= ec) return;
        int src;
        if (g_is64) src = (int)__ldg(&((const long long*)ei)[e]);
        else        src = __ldg(&((const int*)ei)[e]);
        float4 a = __ldg(&attr[e]);
        float* s = (float*)(g_S + (size_t)src * 2);
        asm volatile("red.global.add.v4.f32 [%0], {%1,%2,%3,%4};"
                     :: "l"(s), "f"(a.x), "f"(a.y), "f"(a.z), "f"(a.w) : "memory");
        asm volatile("red.global.add.f32 [%0], %1;"
                     :: "l"(s + 4), "f"(1.0f) : "memory");
        return;
    }

    __shared__ float sW[720], sB[180], sWr[180], sBB[16];
    __shared__ float sx[128 * 18];
    for (int i = threadIdx.x; i < 720; i += blockDim.x) sW[i] = W1e[i];
    for (int i = threadIdx.x; i < 180; i += blockDim.x) { sB[i] = b1e[i]; sWr[i] = Wr1[i]; }
    if (threadIdx.x < 10) sBB[threadIdx.x] = bb1[threadIdx.x];

    int nd0 = blockIdx.x * 128;
    int cnt = n - nd0; if (cnt > 128) cnt = 128;
    for (int i = threadIdx.x; i < cnt * 18; i += blockDim.x)
        sx[i] = __ldg(&x[(size_t)nd0 * 18 + i]);
    __syncthreads();

    int ndl  = threadIdx.x >> 1;
    int half = threadIdx.x & 1;
    if (ndl >= cnt) return;
    int nd = nd0 + ndl;

    float xv[18];
    #pragma unroll
    for (int i = 0; i < 18; i++) xv[i] = sx[ndl * 18 + i];

    __half*  ph   = (__half*)(g_P1h + (size_t)nd * 8) + 32 * half;
    __half2* ph2  = (__half2*)ph;
    float*   hrow = (float*)(g_h1 + (size_t)nd * 4) + 8 * half;

    int o0 = half * 5;
    #pragma unroll
    for (int oo = 0; oo < 5; oo++) {
        int o = o0 + oo;
        float p0 = 0.f, p1 = 0.f, p2 = 0.f, p3 = 0.f, q = 0.f, h = 0.f;
        #pragma unroll
        for (int i = 0; i < 18; i++) {
            int r = i * 10 + o;
            float xi = xv[i];
            p0 += xi * sW[r * 4 + 0];
            p1 += xi * sW[r * 4 + 1];
            p2 += xi * sW[r * 4 + 2];
            p3 += xi * sW[r * 4 + 3];
            q  += xi * sB[r];
            h  += xi * sWr[r];
        }
        ph2[oo * 2 + 0] = __floats2half2_rn(p0, p1);
        ph2[oo * 2 + 1] = __floats2half2_rn(p2, p3);
        ph[20 + oo]     = __float2half_rn(q);
        hrow[oo]        = h + sBB[o];
    }
}

// ---------------------------------------------------------------------------
// k_tail: 2 lanes per edge/node (parity p owns channels 5p..5p+4).
// Edge loop loads S cooperatively: lane p fetches 16B chunk p, pair exchanges
// via shfl_xor(1) -> one S load instruction per edge instead of two.
// ---------------------------------------------------------------------------
__global__ __launch_bounds__(256, 3)
void k_tail(const void* __restrict__ ei, const float4* __restrict__ attr,
            const float* __restrict__ Wr2, const float* __restrict__ bb2,
            const float* __restrict__ W2e, const float* __restrict__ b2e,
            const float* __restrict__ w1, const float* __restrict__ bw1,
            const float* __restrict__ w2, const float* __restrict__ bw2,
            const float* __restrict__ w3, const float* __restrict__ bw3,
            float* __restrict__ out, int n, int ec, int out_size)
{
    __shared__ float s_acc[64];
    if (threadIdx.x < 64) s_acc[threadIdx.x] = 0.f;
    __syncthreads();

    const int is64 = g_is64;
    const int p = threadIdx.x & 1;
    const int pairId = (blockIdx.x * blockDim.x + threadIdx.x) >> 1;
    const int pairStride = (gridDim.x * blockDim.x) >> 1;

    float v[5];
    float T[25];
    #pragma unroll
    for (int i = 0; i < 5; i++) v[i] = 0.f;
    #pragma unroll
    for (int i = 0; i < 25; i++) T[i] = 0.f;

    // ---- root contribution (parity-split stream) ----
    for (int nd = pairId; nd < n; nd += pairStride) {
        const float* hr = (const float*)(g_h1 + (size_t)nd * 4) + 8 * p;
        float4 h4 = __ldg((const float4*)hr);
        float  h5 = __ldg(hr + 4);
        const float* sr = (const float*)(g_S + (size_t)nd * 2);
        float4 s4 = __ldg((const float4*)sr);
        float  sd = __ldg(sr + 4);
        float hv[5] = {h4.x, h4.y, h4.z, h4.w, h5};
        #pragma unroll
        for (int oo = 0; oo < 5; oo++) {
            float hi = hv[oo];
            v[oo] += hi;
            T[oo * 5 + 0] += hi * s4.x;
            T[oo * 5 + 1] += hi * s4.y;
            T[oo * 5 + 2] += hi * s4.z;
            T[oo * 5 + 3] += hi * s4.w;
            T[oo * 5 + 4] += hi * sd;
        }
    }

    // ---- message contribution (2 lanes per edge) ----
    for (int e = pairId; e < ec; e += pairStride) {
        int src, tgt;
        if (is64) {
            src = (int)__ldg(&((const long long*)ei)[e]);
            tgt = (int)__ldg(&((const long long*)ei)[(size_t)ec + e]);
        } else {
            src = __ldg(&((const int*)ei)[e]);
            tgt = __ldg(&((const int*)ei)[(size_t)ec + e]);
        }
        float4 a = __ldg(&attr[e]);

        const char* base = (const char*)(g_P1h + (size_t)src * 8) + 64 * p;
        float4 A = __ldg((const float4*)base);
        float4 B = __ldg((const float4*)(base + 16));
        float4 C = __ldg((const float4*)(base + 32));
        unsigned int qw = __ldg((const unsigned int*)(base + 48));

        // cooperative S load: lane p grabs 16B chunk p of the 32B row,
        // pair exchanges via shfl (same tgt for both lanes of the pair).
        const float* sr = (const float*)(g_S + (size_t)tgt * 2);
        float4 Ls = __ldg((const float4*)(sr + 4 * p));
        float ox = __shfl_xor_sync(0xffffffffu, Ls.x, 1);
        float oy = __shfl_xor_sync(0xffffffffu, Ls.y, 1);
        float oz = __shfl_xor_sync(0xffffffffu, Ls.z, 1);
        float ow = __shfl_xor_sync(0xffffffffu, Ls.w, 1);
        float4 s4;
        float  sd;
        if (p == 0) { s4 = Ls; sd = ox; }
        else        { s4 = make_float4(ox, oy, oz, ow); sd = Ls.x; }

        const __half2* hA = (const __half2*)&A;
        const __half2* hB = (const __half2*)&B;
        const __half2* hC = (const __half2*)&C;

        float2 a0 = __half22float2(hA[0]), a1 = __half22float2(hA[1]);
        float2 a2 = __half22float2(hA[2]), a3 = __half22float2(hA[3]);
        float2 b0 = __half22float2(hB[0]), b1 = __half22float2(hB[1]);
        float2 b2 = __half22float2(hB[2]), b3 = __half22float2(hB[3]);
        float2 c0 = __half22float2(hC[0]), c1 = __half22float2(hC[1]);
        float2 q01 = __half22float2(hC[2]);
        float2 q23 = __half22float2(hC[3]);
        __half2 q4h = *(const __half2*)&qw;
        float q4 = __low2float(q4h);

        float m[5];
        m[0] = a.x * a0.x + a.y * a0.y + a.z * a1.x + a.w * a1.y + q01.x;
        m[1] = a.x * a2.x + a.y * a2.y + a.z * a3.x + a.w * a3.y + q01.y;
        m[2] = a.x * b0.x + a.y * b0.y + a.z * b1.x + a.w * b1.y + q23.x;
        m[3] = a.x * b2.x + a.y * b2.y + a.z * b3.x + a.w * b3.y + q23.y;
        m[4] = a.x * c0.x + a.y * c0.y + a.z * c1.x + a.w * c1.y + q4;

        #pragma unroll
        for (int oo = 0; oo < 5; oo++) {
            float mi = m[oo];
            v[oo] += mi;
            T[oo * 5 + 0] += mi * s4.x;
            T[oo * 5 + 1] += mi * s4.y;
            T[oo * 5 + 2] += mi * s4.z;
            T[oo * 5 + 3] += mi * s4.w;
            T[oo * 5 + 4] += mi * sd;
        }
    }

    // ---- reduce: fold lanes of equal parity; lanes 0,1 hold warp totals ----
    #pragma unroll
    for (int off = 2; off <= 16; off <<= 1) {
        #pragma unroll
        for (int i = 0; i < 5; i++)  v[i] += __shfl_xor_sync(0xffffffffu, v[i], off);
        #pragma unroll
        for (int i = 0; i < 25; i++) T[i] += __shfl_xor_sync(0xffffffffu, T[i], off);
    }
    int lane = threadIdx.x & 31;
    if (lane < 2) {
        #pragma unroll
        for (int oo = 0; oo < 5; oo++) {
            int i = 5 * lane + oo;
            atomicAdd(&s_acc[i], v[oo]);
            #pragma unroll
            for (int k = 0; k < 5; k++)
                atomicAdd(&s_acc[10 + i * 5 + k], T[oo * 5 + k]);
        }
    }
    __syncthreads();
    if (threadIdx.x < 60) atomicAdd(&g_red[threadIdx.x], s_acc[threadIdx.x]);
    __threadfence();
    __syncthreads();

    // ---- last block: MLP ----
    __shared__ int isLast;
    if (threadIdx.x == 0) {
        unsigned int prev = atomicAdd(&g_count, 1u);
        isLast = (prev == gridDim.x - 1) ? 1 : 0;
    }
    __syncthreads();
    if (!isLast) return;

    volatile float* gr = g_red;
    __shared__ float g[8];
    float invn = 1.0f / (float)n;
    if (threadIdx.x < 7) {
        int o = threadIdx.x;
        float s = (float)n * bb2[o];
        #pragma unroll
        for (int i = 0; i < 10; i++) {
            float vi = gr[i];
            s += vi * Wr2[i * 7 + o];
            int rr = i * 7 + o;
            #pragma unroll
            for (int k = 0; k < 4; k++) s += gr[10 + i * 5 + k] * W2e[rr * 4 + k];
            s += gr[10 + i * 5 + 4] * b2e[rr];
        }
        g[o] = s * invn;
    }
    __syncthreads();
    if (threadIdx.x == 0) {
        float gg[7];
        #pragma unroll
        for (int k = 0; k < 7; k++) gg[k] = g[k];
        float g1[20];
        for (int j = 0; j < 20; j++) {
            float val = bw1[j];
            #pragma unroll
            for (int k = 0; k < 7; k++) val += gg[k] * w1[j * 7 + k];
            g1[j] = val > 0.f ? val : 0.f;
        }
        float g2[10];
        for (int j = 0; j < 10; j++) {
            float val = bw2[j];
            #pragma unroll
            for (int k = 0; k < 20; k++) val += g1[k] * w2[j * 20 + k];
            g2[j] = val > 0.f ? val : 0.f;
        }
        float z = bw3[0];
        #pragma unroll
        for (int k = 0; k < 10; k++) z += g2[k] * w3[k];
        float r = 1.0f / (1.0f + expf(-z));
        for (int i = 0; i < out_size; i++) out[i] = r;
    }
}

// ---------------------------------------------------------------------------
extern "C" void kernel_launch(void* const* d_in, const int* in_sizes, int n_in,
                              void* d_out, int out_size)
{
    const float*  x    = (const float*)d_in[0];
    const void*   ei   = d_in[1];
    const float4* attr = (const float4*)d_in[2];
    const float* W1e = (const float*)d_in[3];
    const float* b1e = (const float*)d_in[4];
    const float* Wr1 = (const float*)d_in[5];
    const float* bb1 = (const float*)d_in[6];
    const float* W2e = (const float*)d_in[7];
    const float* b2e = (const float*)d_in[8];
    const float* Wr2 = (const float*)d_in[9];
    const float* bb2 = (const float*)d_in[10];
    const float* w1  = (const float*)d_in[11];
    const float* bw1 = (const float*)d_in[12];
    const float* w2  = (const float*)d_in[13];
    const float* bw2 = (const float*)d_in[14];
    const float* w3  = (const float*)d_in[15];
    const float* bw3 = (const float*)d_in[16];

    int n = in_sizes[0] / 18;
    int e = in_sizes[2] / 4;
    if (n > NN) n = NN;
    if (e > NE) e = NE;

    const int T = 256;
    int nodeBlocks = (n + 127) / 128;
    int edgeBlocks = (e + T - 1) / T;

    k_zero<<<256, T>>>(ei, e, n);
    k_mid<<<nodeBlocks + edgeBlocks, T>>>(x, W1e, b1e, Wr1, bb1, ei, attr,
                                          n, e, nodeBlocks);
    k_tail<<<444, T>>>(ei, attr, Wr2, bb2, W2e, b2e, w1, bw1, w2, bw2, w3, bw3,
                       (float*)d_out, n, e, out_size);
}

// round 15
// speedup vs baseline: 1.3896x; 1.0169x over previous
#include <cuda_runtime.h>
#include <cuda_fp16.h>

#define NN 100000
#define NE 1000000

// Scratch.
// P1h row (128B, 64 halfs) parity-split: half p (byte offset 64p) holds
//   halfs[0..19]  = P[5p+oo][k]  (oo<5, k<4, index oo*4+k)
//   halfs[20..24] = Q[5p+oo]
//   halfs[25..31] = pad
// g_h1 row (16 floats) parity-split: floats[8p+oo] = root1[5p+oo] (oo<5)
// g_S row: attr-sum[0..3], deg at [4] (zeroed by in-graph memset node)
__device__ float4 g_P1h[(size_t)NN * 8];
__device__ float4 g_h1 [(size_t)NN * 4];
__device__ float4 g_S  [(size_t)NN * 2];
__device__ float  g_red[64];  // v[i]=g_red[i] (i<10); T[i][k]=g_red[10+i*5+k]
__device__ unsigned int g_count;

// ---------------------------------------------------------------------------
// Per-warp dtype sniff: int64 iff the first 32 int64-interpreted entries are
// all in [0, n). (int32 data viewed as int64 fuses two random indices ->
// ~2^48 magnitude -> fails with overwhelming probability.)
// ---------------------------------------------------------------------------
__device__ __forceinline__ int sniff_is64(const void* ei, int ec, int n)
{
    const long long* p = (const long long*)ei;
    int lane = threadIdx.x & 31;
    int m = ec < 32 ? ec : 32;
    long long v = __ldg(&p[lane < m ? lane : 0]);
    unsigned bad = __ballot_sync(0xffffffffu, v < 0 || v >= n);
    return bad == 0u;
}

// ---------------------------------------------------------------------------
// k_mid: block-role split.
//  node role: 128 nodes/block, 2 thr/node (thread = one parity half):
//    writes parity-split P/Q (fp16) and parity-split root1 (f32).
//    Block 0 also zeroes g_red + g_count (consumed only by k_tail).
//  edge role: S[src] += (attr, 1) via vectorized REDs (self-sniffed dtype).
// ---------------------------------------------------------------------------
__global__ void k_mid(const float* __restrict__ x,
                      const float* __restrict__ W1e, const float* __restrict__ b1e,
                      const float* __restrict__ Wr1, const float* __restrict__ bb1,
                      const void* __restrict__ ei, const float4* __restrict__ attr,
                      int n, int ec, int nodeBlocks)
{
    if (blockIdx.x >= nodeBlocks) {
        int is64 = sniff_is64(ei, ec, n);
        int e = (blockIdx.x - nodeBlocks) * blockDim.x + threadIdx.x;
        if (e >= ec) return;
        int src;
        if (is64) src = (int)__ldg(&((const long long*)ei)[e]);
        else      src = __ldg(&((const int*)ei)[e]);
        float4 a = __ldg(&attr[e]);
        float* s = (float*)(g_S + (size_t)src * 2);
        asm volatile("red.global.add.v4.f32 [%0], {%1,%2,%3,%4};"
                     :: "l"(s), "f"(a.x), "f"(a.y), "f"(a.z), "f"(a.w) : "memory");
        asm volatile("red.global.add.f32 [%0], %1;"
                     :: "l"(s + 4), "f"(1.0f) : "memory");
        return;
    }

    if (blockIdx.x == 0) {
        if (threadIdx.x < 64) g_red[threadIdx.x] = 0.f;
        if (threadIdx.x == 64) g_count = 0u;
    }

    __shared__ float sW[720], sB[180], sWr[180], sBB[16];
    __shared__ float sx[128 * 18];
    for (int i = threadIdx.x; i < 720; i += blockDim.x) sW[i] = W1e[i];
    for (int i = threadIdx.x; i < 180; i += blockDim.x) { sB[i] = b1e[i]; sWr[i] = Wr1[i]; }
    if (threadIdx.x < 10) sBB[threadIdx.x] = bb1[threadIdx.x];

    int nd0 = blockIdx.x * 128;
    int cnt = n - nd0; if (cnt > 128) cnt = 128;
    for (int i = threadIdx.x; i < cnt * 18; i += blockDim.x)
        sx[i] = __ldg(&x[(size_t)nd0 * 18 + i]);
    __syncthreads();

    int ndl  = threadIdx.x >> 1;
    int half = threadIdx.x & 1;
    if (ndl >= cnt) return;
    int nd = nd0 + ndl;

    float xv[18];
    #pragma unroll
    for (int i = 0; i < 18; i++) xv[i] = sx[ndl * 18 + i];

    __half*  ph   = (__half*)(g_P1h + (size_t)nd * 8) + 32 * half;
    __half2* ph2  = (__half2*)ph;
    float*   hrow = (float*)(g_h1 + (size_t)nd * 4) + 8 * half;

    int o0 = half * 5;
    #pragma unroll
    for (int oo = 0; oo < 5; oo++) {
        int o = o0 + oo;
        float p0 = 0.f, p1 = 0.f, p2 = 0.f, p3 = 0.f, q = 0.f, h = 0.f;
        #pragma unroll
        for (int i = 0; i < 18; i++) {
            int r = i * 10 + o;
            float xi = xv[i];
            p0 += xi * sW[r * 4 + 0];
            p1 += xi * sW[r * 4 + 1];
            p2 += xi * sW[r * 4 + 2];
            p3 += xi * sW[r * 4 + 3];
            q  += xi * sB[r];
            h  += xi * sWr[r];
        }
        ph2[oo * 2 + 0] = __floats2half2_rn(p0, p1);
        ph2[oo * 2 + 1] = __floats2half2_rn(p2, p3);
        ph[20 + oo]     = __float2half_rn(q);
        hrow[oo]        = h + sBB[o];
    }
}

// ---------------------------------------------------------------------------
// k_tail: 2 lanes per edge/node (parity p owns channels 5p..5p+4).
// Edge loop loads S cooperatively: lane p fetches 16B chunk p, pair exchanges
// via shfl_xor(1) -> one S load instruction per edge instead of two.
// ---------------------------------------------------------------------------
__global__ __launch_bounds__(256, 3)
void k_tail(const void* __restrict__ ei, const float4* __restrict__ attr,
            const float* __restrict__ Wr2, const float* __restrict__ bb2,
            const float* __restrict__ W2e, const float* __restrict__ b2e,
            const float* __restrict__ w1, const float* __restrict__ bw1,
            const float* __restrict__ w2, const float* __restrict__ bw2,
            const float* __restrict__ w3, const float* __restrict__ bw3,
            float* __restrict__ out, int n, int ec, int out_size)
{
    __shared__ float s_acc[64];
    if (threadIdx.x < 64) s_acc[threadIdx.x] = 0.f;
    __syncthreads();

    const int is64 = sniff_is64(ei, ec, n);
    const int p = threadIdx.x & 1;
    const int pairId = (blockIdx.x * blockDim.x + threadIdx.x) >> 1;
    const int pairStride = (gridDim.x * blockDim.x) >> 1;

    float v[5];
    float T[25];
    #pragma unroll
    for (int i = 0; i < 5; i++) v[i] = 0.f;
    #pragma unroll
    for (int i = 0; i < 25; i++) T[i] = 0.f;

    // ---- root contribution (parity-split stream) ----
    for (int nd = pairId; nd < n; nd += pairStride) {
        const float* hr = (const float*)(g_h1 + (size_t)nd * 4) + 8 * p;
        float4 h4 = __ldg((const float4*)hr);
        float  h5 = __ldg(hr + 4);
        const float* sr = (const float*)(g_S + (size_t)nd * 2);
        float4 s4 = __ldg((const float4*)sr);
        float  sd = __ldg(sr + 4);
        float hv[5] = {h4.x, h4.y, h4.z, h4.w, h5};
        #pragma unroll
        for (int oo = 0; oo < 5; oo++) {
            float hi = hv[oo];
            v[oo] += hi;
            T[oo * 5 + 0] += hi * s4.x;
            T[oo * 5 + 1] += hi * s4.y;
            T[oo * 5 + 2] += hi * s4.z;
            T[oo * 5 + 3] += hi * s4.w;
            T[oo * 5 + 4] += hi * sd;
        }
    }

    // ---- message contribution (2 lanes per edge) ----
    for (int e = pairId; e < ec; e += pairStride) {
        int src, tgt;
        if (is64) {
            src = (int)__ldg(&((const long long*)ei)[e]);
            tgt = (int)__ldg(&((const long long*)ei)[(size_t)ec + e]);
        } else {
            src = __ldg(&((const int*)ei)[e]);
            tgt = __ldg(&((const int*)ei)[(size_t)ec + e]);
        }
        float4 a = __ldg(&attr[e]);

        const char* base = (const char*)(g_P1h + (size_t)src * 8) + 64 * p;
        float4 A = __ldg((const float4*)base);
        float4 B = __ldg((const float4*)(base + 16));
        float4 C = __ldg((const float4*)(base + 32));
        unsigned int qw = __ldg((const unsigned int*)(base + 48));

        // cooperative S load: lane p grabs 16B chunk p of the 32B row,
        // pair exchanges via shfl (same tgt for both lanes of the pair).
        const float* sr = (const float*)(g_S + (size_t)tgt * 2);
        float4 Ls = __ldg((const float4*)(sr + 4 * p));
        float ox = __shfl_xor_sync(0xffffffffu, Ls.x, 1);
        float oy = __shfl_xor_sync(0xffffffffu, Ls.y, 1);
        float oz = __shfl_xor_sync(0xffffffffu, Ls.z, 1);
        float ow = __shfl_xor_sync(0xffffffffu, Ls.w, 1);
        float4 s4;
        float  sd;
        if (p == 0) { s4 = Ls; sd = ox; }
        else        { s4 = make_float4(ox, oy, oz, ow); sd = Ls.x; }

        const __half2* hA = (const __half2*)&A;
        const __half2* hB = (const __half2*)&B;
        const __half2* hC = (const __half2*)&C;

        float2 a0 = __half22float2(hA[0]), a1 = __half22float2(hA[1]);
        float2 a2 = __half22float2(hA[2]), a3 = __half22float2(hA[3]);
        float2 b0 = __half22float2(hB[0]), b1 = __half22float2(hB[1]);
        float2 b2 = __half22float2(hB[2]), b3 = __half22float2(hB[3]);
        float2 c0 = __half22float2(hC[0]), c1 = __half22float2(hC[1]);
        float2 q01 = __half22float2(hC[2]);
        float2 q23 = __half22float2(hC[3]);
        __half2 q4h = *(const __half2*)&qw;
        float q4 = __low2float(q4h);

        float m[5];
        m[0] = a.x * a0.x + a.y * a0.y + a.z * a1.x + a.w * a1.y + q01.x;
        m[1] = a.x * a2.x + a.y * a2.y + a.z * a3.x + a.w * a3.y + q01.y;
        m[2] = a.x * b0.x + a.y * b0.y + a.z * b1.x + a.w * b1.y + q23.x;
        m[3] = a.x * b2.x + a.y * b2.y + a.z * b3.x + a.w * b3.y + q23.y;
        m[4] = a.x * c0.x + a.y * c0.y + a.z * c1.x + a.w * c1.y + q4;

        #pragma unroll
        for (int oo = 0; oo < 5; oo++) {
            float mi = m[oo];
            v[oo] += mi;
            T[oo * 5 + 0] += mi * s4.x;
            T[oo * 5 + 1] += mi * s4.y;
            T[oo * 5 + 2] += mi * s4.z;
            T[oo * 5 + 3] += mi * s4.w;
            T[oo * 5 + 4] += mi * sd;
        }
    }

    // ---- reduce: fold lanes of equal parity; lanes 0,1 hold warp totals ----
    #pragma unroll
    for (int off = 2; off <= 16; off <<= 1) {
        #pragma unroll
        for (int i = 0; i < 5; i++)  v[i] += __shfl_xor_sync(0xffffffffu, v[i], off);
        #pragma unroll
        for (int i = 0; i < 25; i++) T[i] += __shfl_xor_sync(0xffffffffu, T[i], off);
    }
    int lane = threadIdx.x & 31;
    if (lane < 2) {
        #pragma unroll
        for (int oo = 0; oo < 5; oo++) {
            int i = 5 * lane + oo;
            atomicAdd(&s_acc[i], v[oo]);
            #pragma unroll
            for (int k = 0; k < 5; k++)
                atomicAdd(&s_acc[10 + i * 5 + k], T[oo * 5 + k]);
        }
    }
    __syncthreads();
    if (threadIdx.x < 60) atomicAdd(&g_red[threadIdx.x], s_acc[threadIdx.x]);
    __threadfence();
    __syncthreads();

    // ---- last block: MLP ----
    __shared__ int isLast;
    if (threadIdx.x == 0) {
        unsigned int prev = atomicAdd(&g_count, 1u);
        isLast = (prev == gridDim.x - 1) ? 1 : 0;
    }
    __syncthreads();
    if (!isLast) return;

    volatile float* gr = g_red;
    __shared__ float g[8];
    float invn = 1.0f / (float)n;
    if (threadIdx.x < 7) {
        int o = threadIdx.x;
        float s = (float)n * bb2[o];
        #pragma unroll
        for (int i = 0; i < 10; i++) {
            float vi = gr[i];
            s += vi * Wr2[i * 7 + o];
            int rr = i * 7 + o;
            #pragma unroll
            for (int k = 0; k < 4; k++) s += gr[10 + i * 5 + k] * W2e[rr * 4 + k];
            s += gr[10 + i * 5 + 4] * b2e[rr];
        }
        g[o] = s * invn;
    }
    __syncthreads();
    if (threadIdx.x == 0) {
        float gg[7];
        #pragma unroll
        for (int k = 0; k < 7; k++) gg[k] = g[k];
        float g1[20];
        for (int j = 0; j < 20; j++) {
            float val = bw1[j];
            #pragma unroll
            for (int k = 0; k < 7; k++) val += gg[k] * w1[j * 7 + k];
            g1[j] = val > 0.f ? val : 0.f;
        }
        float g2[10];
        for (int j = 0; j < 10; j++) {
            float val = bw2[j];
            #pragma unroll
            for (int k = 0; k < 20; k++) val += g1[k] * w2[j * 20 + k];
            g2[j] = val > 0.f ? val : 0.f;
        }
        float z = bw3[0];
        #pragma unroll
        for (int k = 0; k < 10; k++) z += g2[k] * w3[k];
        float r = 1.0f / (1.0f + expf(-z));
        for (int i = 0; i < out_size; i++) out[i] = r;
    }
}

// ---------------------------------------------------------------------------
extern "C" void kernel_launch(void* const* d_in, const int* in_sizes, int n_in,
                              void* d_out, int out_size)
{
    const float*  x    = (const float*)d_in[0];
    const void*   ei   = d_in[1];
    const float4* attr = (const float4*)d_in[2];
    const float* W1e = (const float*)d_in[3];
    const float* b1e = (const float*)d_in[4];
    const float* Wr1 = (const float*)d_in[5];
    const float* bb1 = (const float*)d_in[6];
    const float* W2e = (const float*)d_in[7];
    const float* b2e = (const float*)d_in[8];
    const float* Wr2 = (const float*)d_in[9];
    const float* bb2 = (const float*)d_in[10];
    const float* w1  = (const float*)d_in[11];
    const float* bw1 = (const float*)d_in[12];
    const float* w2  = (const float*)d_in[13];
    const float* bw2 = (const float*)d_in[14];
    const float* w3  = (const float*)d_in[15];
    const float* bw3 = (const float*)d_in[16];

    int n = in_sizes[0] / 18;
    int e = in_sizes[2] / 4;
    if (n > NN) n = NN;
    if (e > NE) e = NE;

    // In-graph memset node replaces the S-zero kernel (g_red/g_count are
    // zeroed inside k_mid's node role, ordered before k_tail by the kernel
    // boundary).
    void* sPtr = nullptr;
    cudaGetSymbolAddress(&sPtr, g_S);
    cudaMemsetAsync(sPtr, 0, (size_t)n * 2 * sizeof(float4), 0);

    const int T = 256;
    int nodeBlocks = (n + 127) / 128;
    int edgeBlocks = (e + T - 1) / T;

    k_mid<<<nodeBlocks + edgeBlocks, T>>>(x, W1e, b1e, Wr1, bb1, ei, attr,
                                          n, e, nodeBlocks);
    k_tail<<<444, T>>>(ei, attr, Wr2, bb2, W2e, b2e, w1, bw1, w2, bw2, w3, bw3,
                       (float*)d_out, n, e, out_size);
}